// round 2
// baseline (speedup 1.0000x reference)
#include <cuda_runtime.h>
#include <cstdint>

// Problem dims
#define BB 64
#define TT 512
#define EE 768
#define HH 256
#define VV 3072

// Scratch (device globals -- no allocation allowed)
__device__ float g_x[TT * BB * HH];   // xWxh laid out [t][b][h]
__device__ float g_h[BB * HH];        // final hidden

// ---------- f32x2 helpers (Blackwell packed fp32 FMA) ----------
__device__ __forceinline__ unsigned long long pack2(float lo, float hi) {
    unsigned long long r;
    asm("mov.b64 %0, {%1, %2};" : "=l"(r) : "f"(lo), "f"(hi));
    return r;
}
__device__ __forceinline__ void unpack2(unsigned long long v, float& lo, float& hi) {
    asm("mov.b64 {%0, %1}, %2;" : "=f"(lo), "=f"(hi) : "l"(v));
}
__device__ __forceinline__ unsigned long long fma2(unsigned long long a,
                                                   unsigned long long b,
                                                   unsigned long long c) {
    unsigned long long d;
    asm("fma.rn.f32x2 %0, %1, %2, %3;" : "=l"(d) : "l"(a), "l"(b), "l"(c));
    return d;
}

// =====================================================================
// Phase 1: g_x[t][b][h] = sum_e emb[idx[b][t]][e] * Wxh[e][h]
// M = B*T = 32768 rows (m = b*512 + t), N = 256, K = 768.
// Tiles: BM=128, BN=128, BK=16; 256 threads; 8x8 microtile via f32x2.
// =====================================================================
__global__ __launch_bounds__(256, 2)
void gemm_emb(const int* __restrict__ idx, const float* __restrict__ emb,
              const float* __restrict__ Wxh) {
    __shared__ __align__(16) float As[128][17];   // [m][k], pad to kill conflicts
    __shared__ __align__(16) float Bs[16][128];   // [k][n]
    __shared__ int idx_s[128];

    const int tid = threadIdx.x;
    const int bm = blockIdx.y;   // 0..255
    const int bn = blockIdx.x;   // 0..1

    if (tid < 128) idx_s[tid] = idx[bm * 128 + tid];
    __syncthreads();

    const int tx = tid & 15;     // micro col group
    const int ty = tid >> 4;     // micro row group

    // A-load mapping: 2 rows per thread, float4 columns
    const int ar = tid >> 2;            // 0..63
    const int ac = (tid & 3) * 4;       // 0,4,8,12
    const float* arow0 = emb + (size_t)idx_s[ar] * EE;
    const float* arow1 = emb + (size_t)idx_s[ar + 64] * EE;

    // B-load mapping
    const int bkr = tid >> 5;           // 0..7
    const int bc  = (tid & 31) * 4;     // 0..124

    unsigned long long c2[8][4];
#pragma unroll
    for (int i = 0; i < 8; i++)
#pragma unroll
        for (int j = 0; j < 4; j++) c2[i][j] = 0ull;

    const uint32_t bs_base = (uint32_t)__cvta_generic_to_shared(&Bs[0][0]) + tx * 32;

    for (int kk = 0; kk < EE; kk += 16) {
        // Load A tile (gathered)
        {
            float4 v0 = *reinterpret_cast<const float4*>(arow0 + kk + ac);
            float4 v1 = *reinterpret_cast<const float4*>(arow1 + kk + ac);
            As[ar][ac + 0] = v0.x; As[ar][ac + 1] = v0.y;
            As[ar][ac + 2] = v0.z; As[ar][ac + 3] = v0.w;
            As[ar + 64][ac + 0] = v1.x; As[ar + 64][ac + 1] = v1.y;
            As[ar + 64][ac + 2] = v1.z; As[ar + 64][ac + 3] = v1.w;
        }
        // Load B tile
#pragma unroll
        for (int rr = 0; rr < 2; rr++) {
            int k = bkr + rr * 8;
            float4 v = *reinterpret_cast<const float4*>(
                Wxh + (size_t)(kk + k) * HH + bn * 128 + bc);
            *reinterpret_cast<float4*>(&Bs[k][bc]) = v;
        }
        __syncthreads();

#pragma unroll
        for (int k = 0; k < 16; k++) {
            unsigned long long b2[4];
            uint32_t ba = bs_base + k * 512;
            asm volatile("ld.shared.v2.u64 {%0,%1}, [%2];"
                         : "=l"(b2[0]), "=l"(b2[1]) : "r"(ba));
            asm volatile("ld.shared.v2.u64 {%0,%1}, [%2];"
                         : "=l"(b2[2]), "=l"(b2[3]) : "r"(ba + 16));
#pragma unroll
            for (int i = 0; i < 8; i++) {
                float a = As[ty * 8 + i][k];
                unsigned long long a2 = pack2(a, a);
#pragma unroll
                for (int j = 0; j < 4; j++) c2[i][j] = fma2(a2, b2[j], c2[i][j]);
            }
        }
        __syncthreads();
    }

    // Epilogue: m = b*512 + t  ->  g_x[t*B*H + b*H + h]
#pragma unroll
    for (int i = 0; i < 8; i++) {
        int m = bm * 128 + ty * 8 + i;
        int b = m >> 9;
        int t = m & 511;
        float* outp = g_x + (size_t)t * (BB * HH) + b * HH + bn * 128 + tx * 8;
        float4 v0, v1;
        unpack2(c2[i][0], v0.x, v0.y); unpack2(c2[i][1], v0.z, v0.w);
        unpack2(c2[i][2], v1.x, v1.y); unpack2(c2[i][3], v1.z, v1.w);
        *reinterpret_cast<float4*>(outp)     = v0;
        *reinterpret_cast<float4*>(outp + 4) = v1;
    }
}

// =====================================================================
// Phase 2: recurrent scan. Cluster of 2 CTAs per batch row.
// CTA rank r owns output columns j = r*128 .. r*128+127.
// 512 threads = 128 j_local x 4 i-chunks of 64. Whh half lives in regs
// as f32x2 pairs (32 x b64 per thread). h exchanged via DSMEM each step.
// =====================================================================
__global__ __launch_bounds__(512, 1) __cluster_dims__(2, 1, 1)
void rnn_scan(const float* __restrict__ Whh, const float* __restrict__ Bh) {
    __shared__ __align__(16) float hbuf[2][256];
    __shared__ float psum[3][128];

    const int tid = threadIdx.x;
    const int b = blockIdx.x >> 1;
    uint32_t rank;
    asm("mov.u32 %0, %%cluster_ctarank;" : "=r"(rank));

    const int jl = tid & 127;        // local j
    const int c  = tid >> 7;         // i-chunk 0..3
    const int j  = (int)rank * 128 + jl;  // global j

    // Load weight pairs: i = c*64 + 2p (+1)
    unsigned long long w2[32];
#pragma unroll
    for (int p = 0; p < 32; p++) {
        int i = c * 64 + 2 * p;
        w2[p] = pack2(Whh[i * HH + j], Whh[(i + 1) * HH + j]);
    }
    float bh = 0.f;
    if (c == 0) bh = Bh[j];

    if (tid < 256) hbuf[0][tid] = 0.f;
    __syncthreads();
    asm volatile("barrier.cluster.arrive.aligned;" ::: "memory");
    asm volatile("barrier.cluster.wait.aligned;"   ::: "memory");

    const uint32_t hbase = (uint32_t)__cvta_generic_to_shared(&hbuf[0][0]);
    const float* xptr = g_x + b * HH + j;

    for (int t = 0; t < TT; t++) {
        const int cur = t & 1;
        const int nb  = cur ^ 1;

        float xv = 0.f;
        if (c == 0) xv = xptr[(size_t)t * (BB * HH)];   // prefetch early

        uint32_t ha = hbase + cur * 1024 + c * 256;
        unsigned long long acc0 = 0ull, acc1 = 0ull;
#pragma unroll
        for (int p = 0; p < 8; p++) {
            unsigned long long h0, h1, h2, h3;
            asm volatile("ld.shared.v2.u64 {%0,%1}, [%2];"
                         : "=l"(h0), "=l"(h1) : "r"(ha + p * 32));
            asm volatile("ld.shared.v2.u64 {%0,%1}, [%2];"
                         : "=l"(h2), "=l"(h3) : "r"(ha + p * 32 + 16));
            acc0 = fma2(w2[4 * p + 0], h0, acc0);
            acc1 = fma2(w2[4 * p + 1], h1, acc1);
            acc0 = fma2(w2[4 * p + 2], h2, acc0);
            acc1 = fma2(w2[4 * p + 3], h3, acc1);
        }
        float l0, u0, l1, u1;
        unpack2(acc0, l0, u0); unpack2(acc1, l1, u1);
        float part = (l0 + u0) + (l1 + u1);

        if (c > 0) psum[c - 1][jl] = part;
        __syncthreads();

        if (c == 0) {
            float s = part + psum[0][jl] + psum[1][jl] + psum[2][jl] + xv + bh;
            float hn = tanhf(s);
            hbuf[nb][j] = hn;
            // push my half to the peer CTA's hbuf[nb][j]
            uint32_t my = hbase + nb * 1024 + j * 4;
            uint32_t peer;
            asm("mapa.shared::cluster.u32 %0, %1, %2;"
                : "=r"(peer) : "r"(my), "r"(rank ^ 1u));
            asm volatile("st.shared::cluster.f32 [%0], %1;" :: "r"(peer), "f"(hn));
        }
        asm volatile("barrier.cluster.arrive.aligned;" ::: "memory");
        asm volatile("barrier.cluster.wait.aligned;"   ::: "memory");
    }

    // TT even -> final hidden in hbuf[0]
    if (c == 0) g_h[b * HH + j] = hbuf[0][j];
}

// =====================================================================
// Phase 3: out[b][v] = sum_h g_h[b][h] * Wy[h][v] + By[v]
// Grid: 64 b x 12 v-tiles (256 wide) = 768 CTAs; CTA 768 copies hidden.
// =====================================================================
__global__ __launch_bounds__(256)
void out_proj(const float* __restrict__ Wy, const float* __restrict__ By,
              float* __restrict__ out, int out_size) {
    if (blockIdx.x == 768) {
        if (out_size >= BB * VV + BB * HH) {
            for (int i = threadIdx.x; i < BB * HH; i += 256)
                out[BB * VV + i] = g_h[i];
        }
        return;
    }
    __shared__ float hs[HH];
    const int b  = blockIdx.x / 12;
    const int vt = blockIdx.x % 12;
    const int v  = vt * 256 + threadIdx.x;

    if (threadIdx.x < HH) hs[threadIdx.x] = g_h[b * HH + threadIdx.x];
    __syncthreads();

    float acc = 0.f;
#pragma unroll 8
    for (int h = 0; h < HH; h++) acc += hs[h] * Wy[(size_t)h * VV + v];

    out[(size_t)b * VV + v] = acc + By[v];
}

// =====================================================================
extern "C" void kernel_launch(void* const* d_in, const int* in_sizes, int n_in,
                              void* d_out, int out_size) {
    const int*   idx = (const int*)d_in[0];
    const float* emb = (const float*)d_in[1];
    const float* Wxh = (const float*)d_in[2];
    const float* Whh = (const float*)d_in[3];
    const float* Wy  = (const float*)d_in[4];
    const float* By  = (const float*)d_in[5];
    const float* Bh  = (const float*)d_in[6];
    float* out = (float*)d_out;

    gemm_emb<<<dim3(2, 256), 256>>>(idx, emb, Wxh);
    rnn_scan<<<128, 512>>>(Whh, Bh);
    out_proj<<<769, 256>>>(Wy, By, out, out_size);
}